// round 10
// baseline (speedup 1.0000x reference)
#include <cuda_runtime.h>

#define B_  4
#define T_  2048
#define D_  1024
#define H_  16
#define DH_ 64
#define M_  (B_*T_)   // 8192

// Scratch (allocation-free rule: device globals)
__device__ float g_q[B_*H_*T_*DH_];
__device__ float g_k[B_*H_*T_*DH_];
__device__ float g_v[B_*H_*T_*DH_];
__device__ float g_ctx[M_*D_];

// ---------------------------------------------------------------------------
// GEMM: C[M,N] = A[M,K] @ W[N,K]^T + bias[N]
// MODE 0: A = x param, scatter result into g_q/g_k/g_v ([B,H,T,dh])
// MODE 1: A = g_ctx,   write result into C param (plain row-major)
// 64x64 tile, BK=16, 256 threads, 4x4 per-thread tile.
// ---------------------------------------------------------------------------
template<int MODE>
__global__ __launch_bounds__(256)
void gemm_kernel(const float* __restrict__ A, const float* __restrict__ W,
                 const float* __restrict__ bias, float* __restrict__ C,
                 int M, int N, int K)
{
    __shared__ float As[16][64];   // [k][m]
    __shared__ float Bs[16][64];   // [k][n]

    const float* Ap = (MODE == 1) ? (const float*)g_ctx : A;

    int tid = threadIdx.x;
    int tx = tid & 15;
    int ty = tid >> 4;
    int m0 = blockIdx.y * 64;
    int n0 = blockIdx.x * 64;

    int lr = tid >> 2;          // 0..63 row within tile
    int lc = (tid & 3) << 2;    // 0,4,8,12 col within BK

    float acc[4][4] = {};

    for (int kt = 0; kt < K; kt += 16) {
        float4 a4 = *(const float4*)&Ap[(size_t)(m0 + lr) * K + kt + lc];
        float4 b4 = *(const float4*)&W [(size_t)(n0 + lr) * K + kt + lc];
        As[lc + 0][lr] = a4.x; As[lc + 1][lr] = a4.y;
        As[lc + 2][lr] = a4.z; As[lc + 3][lr] = a4.w;
        Bs[lc + 0][lr] = b4.x; Bs[lc + 1][lr] = b4.y;
        Bs[lc + 2][lr] = b4.z; Bs[lc + 3][lr] = b4.w;
        __syncthreads();

        #pragma unroll
        for (int kk = 0; kk < 16; kk++) {
            float4 av = *(const float4*)&As[kk][ty * 4];
            float4 bv = *(const float4*)&Bs[kk][tx * 4];
            float am[4] = {av.x, av.y, av.z, av.w};
            float bm[4] = {bv.x, bv.y, bv.z, bv.w};
            #pragma unroll
            for (int i = 0; i < 4; i++)
                #pragma unroll
                for (int j = 0; j < 4; j++)
                    acc[i][j] = fmaf(am[i], bm[j], acc[i][j]);
        }
        __syncthreads();
    }

    #pragma unroll
    for (int i = 0; i < 4; i++) {
        int m = m0 + ty * 4 + i;
        #pragma unroll
        for (int j = 0; j < 4; j++) {
            int n = n0 + tx * 4 + j;
            float val = acc[i][j] + bias[n];
            if (MODE == 0) {
                // n = which*D + h*64 + d ;  m = b*T + t
                int bb    = m >> 11;        // /2048
                int t     = m & 2047;
                int which = n >> 10;
                int rem   = n & 1023;
                int hh    = rem >> 6;
                int dd    = rem & 63;
                int idx   = ((bb * H_ + hh) * T_ + t) * DH_ + dd;
                float* dst = (which == 0) ? g_q : (which == 1) ? g_k : g_v;
                dst[idx] = val;
            } else {
                C[(size_t)m * N + n] = val;
            }
        }
    }
}

// ---------------------------------------------------------------------------
// Flash attention, fp32. Block = (b, h, 64 q rows). K/V tiles of 64 rows.
// Smem: Qs [d][m] 16KB, KPs (K as [d][n], reused as P [m][n]) 16KB, Vs [n][d]
// 16KB = 48KB exactly. 256 threads: (ty 0..15 -> 4 q rows, tx 0..15 -> 4 cols).
// Row reductions via shfl_xor within 16-lane half-warps (lane = (ty&1)*16+tx).
// ---------------------------------------------------------------------------
__global__ __launch_bounds__(256)
void attn_kernel()
{
    __shared__ float Qs [64][64];   // [d][m]
    __shared__ float KPs[64][64];   // K: [d][n]  ->  P: [m][n]
    __shared__ float Vs [64][64];   // [n][d]

    int tid = threadIdx.x;
    int tx = tid & 15;
    int ty = tid >> 4;
    int b = blockIdx.z;
    int h = blockIdx.y;
    int q0 = blockIdx.x * 64;

    const float* Qg = g_q + (size_t)(b * H_ + h) * T_ * DH_;
    const float* Kg = g_k + (size_t)(b * H_ + h) * T_ * DH_;
    const float* Vg = g_v + (size_t)(b * H_ + h) * T_ * DH_;

    int lr  = tid >> 2;          // 0..63
    int lc0 = (tid & 3) * 16;    // 0,16,32,48

    // Load Q tile, transposed to [d][m]
    #pragma unroll
    for (int j = 0; j < 4; j++) {
        float4 v = *(const float4*)&Qg[(q0 + lr) * DH_ + lc0 + j * 4];
        Qs[lc0 + j*4 + 0][lr] = v.x;
        Qs[lc0 + j*4 + 1][lr] = v.y;
        Qs[lc0 + j*4 + 2][lr] = v.z;
        Qs[lc0 + j*4 + 3][lr] = v.w;
    }

    float m_i[4], l_i[4], o[4][4];
    #pragma unroll
    for (int i = 0; i < 4; i++) {
        m_i[i] = -1e30f;
        l_i[i] = 0.f;
        #pragma unroll
        for (int j = 0; j < 4; j++) o[i][j] = 0.f;
    }

    const float scale = 0.125f;  // 1/sqrt(64)

    for (int k0 = 0; k0 < T_; k0 += 64) {
        __syncthreads();  // prior iter's P/V reads done; also covers Q load on iter 0

        // Load K (transposed [d][n]) and V (natural [n][d])
        #pragma unroll
        for (int j = 0; j < 4; j++) {
            float4 kv = *(const float4*)&Kg[(k0 + lr) * DH_ + lc0 + j * 4];
            KPs[lc0 + j*4 + 0][lr] = kv.x;
            KPs[lc0 + j*4 + 1][lr] = kv.y;
            KPs[lc0 + j*4 + 2][lr] = kv.z;
            KPs[lc0 + j*4 + 3][lr] = kv.w;
            float4 vv = *(const float4*)&Vg[(k0 + lr) * DH_ + lc0 + j * 4];
            *(float4*)&Vs[lr][lc0 + j * 4] = vv;
        }
        __syncthreads();

        // S = Q @ K^T  (4x4 per thread)
        float s[4][4] = {};
        #pragma unroll 8
        for (int d = 0; d < 64; d++) {
            float4 qv = *(const float4*)&Qs[d][ty * 4];
            float4 kv = *(const float4*)&KPs[d][tx * 4];
            float qm[4] = {qv.x, qv.y, qv.z, qv.w};
            float km[4] = {kv.x, kv.y, kv.z, kv.w};
            #pragma unroll
            for (int i = 0; i < 4; i++)
                #pragma unroll
                for (int j = 0; j < 4; j++)
                    s[i][j] = fmaf(qm[i], km[j], s[i][j]);
        }

        __syncthreads();  // everyone done reading KPs as K; safe to overwrite with P

        // Online softmax (row groups = 16 threads sharing ty, lanes (ty&1)*16+tx)
        #pragma unroll
        for (int i = 0; i < 4; i++) {
            float rm = fmaxf(fmaxf(s[i][0], s[i][1]), fmaxf(s[i][2], s[i][3])) * scale;
            rm = fmaxf(rm, __shfl_xor_sync(0xffffffffu, rm, 1));
            rm = fmaxf(rm, __shfl_xor_sync(0xffffffffu, rm, 2));
            rm = fmaxf(rm, __shfl_xor_sync(0xffffffffu, rm, 4));
            rm = fmaxf(rm, __shfl_xor_sync(0xffffffffu, rm, 8));
            float mnew = fmaxf(m_i[i], rm);
            float corr = __expf(m_i[i] - mnew);
            float rs = 0.f;
            #pragma unroll
            for (int j = 0; j < 4; j++) {
                s[i][j] = __expf(fmaf(s[i][j], scale, -mnew));
                rs += s[i][j];
            }
            rs += __shfl_xor_sync(0xffffffffu, rs, 1);
            rs += __shfl_xor_sync(0xffffffffu, rs, 2);
            rs += __shfl_xor_sync(0xffffffffu, rs, 4);
            rs += __shfl_xor_sync(0xffffffffu, rs, 8);
            l_i[i] = l_i[i] * corr + rs;
            m_i[i] = mnew;
            #pragma unroll
            for (int j = 0; j < 4; j++) o[i][j] *= corr;
            // Store P row-major [m][n] — float4, conflict-free
            *(float4*)&KPs[ty * 4 + i][tx * 4] =
                make_float4(s[i][0], s[i][1], s[i][2], s[i][3]);
        }
        __syncthreads();

        // O += P @ V
        #pragma unroll 8
        for (int n = 0; n < 64; n++) {
            float4 vv = *(const float4*)&Vs[n][tx * 4];
            float vm[4] = {vv.x, vv.y, vv.z, vv.w};
            float pm[4];
            #pragma unroll
            for (int i = 0; i < 4; i++) pm[i] = KPs[ty * 4 + i][n];
            #pragma unroll
            for (int i = 0; i < 4; i++)
                #pragma unroll
                for (int j = 0; j < 4; j++)
                    o[i][j] = fmaf(pm[i], vm[j], o[i][j]);
        }
    }

    // Epilogue: normalize and write ctx in [B,T,D] layout
    #pragma unroll
    for (int i = 0; i < 4; i++) {
        float inv = 1.f / l_i[i];
        int t = q0 + ty * 4 + i;
        #pragma unroll
        for (int j = 0; j < 4; j++) {
            g_ctx[(size_t)(b * T_ + t) * D_ + h * DH_ + tx * 4 + j] = o[i][j] * inv;
        }
    }
}

// ---------------------------------------------------------------------------
extern "C" void kernel_launch(void* const* d_in, const int* in_sizes, int n_in,
                              void* d_out, int out_size)
{
    const float* x     = (const float*)d_in[0];
    const float* qkv_w = (const float*)d_in[1];
    const float* qkv_b = (const float*)d_in[2];
    const float* out_w = (const float*)d_in[3];
    const float* out_b = (const float*)d_in[4];
    float* out = (float*)d_out;

    // QKV projection + scatter: M=8192, N=3072, K=1024
    gemm_kernel<0><<<dim3(3 * D_ / 64, M_ / 64), 256>>>(
        x, qkv_w, qkv_b, nullptr, M_, 3 * D_, D_);

    // Flash attention: grid (T/64, H, B)
    attn_kernel<<<dim3(T_ / 64, H_, B_), 256>>>();

    // Output projection: M=8192, N=1024, K=1024
    gemm_kernel<1><<<dim3(D_ / 64, M_ / 64), 256>>>(
        nullptr, out_w, out_b, out, M_, D_, D_);
}

// round 11
// speedup vs baseline: 1.0002x; 1.0002x over previous
#include <cuda_runtime.h>

#define B_  4
#define T_  2048
#define D_  1024
#define H_  16
#define DH_ 64
#define M_  (B_*T_)   // 8192

// Scratch (allocation-free rule: device globals)
__device__ float g_q[B_*H_*T_*DH_];
__device__ float g_k[B_*H_*T_*DH_];
__device__ float g_v[B_*H_*T_*DH_];
__device__ float g_ctx[M_*D_];

// ---------------------------------------------------------------------------
// GEMM: C[M,N] = A[M,K] @ W[N,K]^T + bias[N]
// MODE 0: A = x param, scatter result into g_q/g_k/g_v ([B,H,T,dh])
// MODE 1: A = g_ctx,   write result into C param (plain row-major)
// 64x64 tile, BK=16, 256 threads, 4x4 per-thread tile.
// ---------------------------------------------------------------------------
template<int MODE>
__global__ __launch_bounds__(256)
void gemm_kernel(const float* __restrict__ A, const float* __restrict__ W,
                 const float* __restrict__ bias, float* __restrict__ C,
                 int M, int N, int K)
{
    __shared__ float As[16][64];   // [k][m]
    __shared__ float Bs[16][64];   // [k][n]

    const float* Ap = (MODE == 1) ? (const float*)g_ctx : A;

    int tid = threadIdx.x;
    int tx = tid & 15;
    int ty = tid >> 4;
    int m0 = blockIdx.y * 64;
    int n0 = blockIdx.x * 64;

    int lr = tid >> 2;          // 0..63 row within tile
    int lc = (tid & 3) << 2;    // 0,4,8,12 col within BK

    float acc[4][4] = {};

    for (int kt = 0; kt < K; kt += 16) {
        float4 a4 = *(const float4*)&Ap[(size_t)(m0 + lr) * K + kt + lc];
        float4 b4 = *(const float4*)&W [(size_t)(n0 + lr) * K + kt + lc];
        As[lc + 0][lr] = a4.x; As[lc + 1][lr] = a4.y;
        As[lc + 2][lr] = a4.z; As[lc + 3][lr] = a4.w;
        Bs[lc + 0][lr] = b4.x; Bs[lc + 1][lr] = b4.y;
        Bs[lc + 2][lr] = b4.z; Bs[lc + 3][lr] = b4.w;
        __syncthreads();

        #pragma unroll
        for (int kk = 0; kk < 16; kk++) {
            float4 av = *(const float4*)&As[kk][ty * 4];
            float4 bv = *(const float4*)&Bs[kk][tx * 4];
            float am[4] = {av.x, av.y, av.z, av.w};
            float bm[4] = {bv.x, bv.y, bv.z, bv.w};
            #pragma unroll
            for (int i = 0; i < 4; i++)
                #pragma unroll
                for (int j = 0; j < 4; j++)
                    acc[i][j] = fmaf(am[i], bm[j], acc[i][j]);
        }
        __syncthreads();
    }

    #pragma unroll
    for (int i = 0; i < 4; i++) {
        int m = m0 + ty * 4 + i;
        #pragma unroll
        for (int j = 0; j < 4; j++) {
            int n = n0 + tx * 4 + j;
            float val = acc[i][j] + bias[n];
            if (MODE == 0) {
                // n = which*D + h*64 + d ;  m = b*T + t
                int bb    = m >> 11;        // /2048
                int t     = m & 2047;
                int which = n >> 10;
                int rem   = n & 1023;
                int hh    = rem >> 6;
                int dd    = rem & 63;
                int idx   = ((bb * H_ + hh) * T_ + t) * DH_ + dd;
                float* dst = (which == 0) ? g_q : (which == 1) ? g_k : g_v;
                dst[idx] = val;
            } else {
                C[(size_t)m * N + n] = val;
            }
        }
    }
}

// ---------------------------------------------------------------------------
// Flash attention, fp32. Block = (b, h, 64 q rows). K/V tiles of 64 rows.
// Smem: Qs [d][m] 16KB, KPs (K as [d][n], reused as P [m][n]) 16KB, Vs [n][d]
// 16KB = 48KB exactly. 256 threads: (ty 0..15 -> 4 q rows, tx 0..15 -> 4 cols).
// Row reductions via shfl_xor within 16-lane half-warps (lane = (ty&1)*16+tx).
// ---------------------------------------------------------------------------
__global__ __launch_bounds__(256)
void attn_kernel()
{
    __shared__ float Qs [64][64];   // [d][m]
    __shared__ float KPs[64][64];   // K: [d][n]  ->  P: [m][n]
    __shared__ float Vs [64][64];   // [n][d]

    int tid = threadIdx.x;
    int tx = tid & 15;
    int ty = tid >> 4;
    int b = blockIdx.z;
    int h = blockIdx.y;
    int q0 = blockIdx.x * 64;

    const float* Qg = g_q + (size_t)(b * H_ + h) * T_ * DH_;
    const float* Kg = g_k + (size_t)(b * H_ + h) * T_ * DH_;
    const float* Vg = g_v + (size_t)(b * H_ + h) * T_ * DH_;

    int lr  = tid >> 2;          // 0..63
    int lc0 = (tid & 3) * 16;    // 0,16,32,48

    // Load Q tile, transposed to [d][m]
    #pragma unroll
    for (int j = 0; j < 4; j++) {
        float4 v = *(const float4*)&Qg[(q0 + lr) * DH_ + lc0 + j * 4];
        Qs[lc0 + j*4 + 0][lr] = v.x;
        Qs[lc0 + j*4 + 1][lr] = v.y;
        Qs[lc0 + j*4 + 2][lr] = v.z;
        Qs[lc0 + j*4 + 3][lr] = v.w;
    }

    float m_i[4], l_i[4], o[4][4];
    #pragma unroll
    for (int i = 0; i < 4; i++) {
        m_i[i] = -1e30f;
        l_i[i] = 0.f;
        #pragma unroll
        for (int j = 0; j < 4; j++) o[i][j] = 0.f;
    }

    const float scale = 0.125f;  // 1/sqrt(64)

    for (int k0 = 0; k0 < T_; k0 += 64) {
        __syncthreads();  // prior iter's P/V reads done; also covers Q load on iter 0

        // Load K (transposed [d][n]) and V (natural [n][d])
        #pragma unroll
        for (int j = 0; j < 4; j++) {
            float4 kv = *(const float4*)&Kg[(k0 + lr) * DH_ + lc0 + j * 4];
            KPs[lc0 + j*4 + 0][lr] = kv.x;
            KPs[lc0 + j*4 + 1][lr] = kv.y;
            KPs[lc0 + j*4 + 2][lr] = kv.z;
            KPs[lc0 + j*4 + 3][lr] = kv.w;
            float4 vv = *(const float4*)&Vg[(k0 + lr) * DH_ + lc0 + j * 4];
            *(float4*)&Vs[lr][lc0 + j * 4] = vv;
        }
        __syncthreads();

        // S = Q @ K^T  (4x4 per thread)
        float s[4][4] = {};
        #pragma unroll 8
        for (int d = 0; d < 64; d++) {
            float4 qv = *(const float4*)&Qs[d][ty * 4];
            float4 kv = *(const float4*)&KPs[d][tx * 4];
            float qm[4] = {qv.x, qv.y, qv.z, qv.w};
            float km[4] = {kv.x, kv.y, kv.z, kv.w};
            #pragma unroll
            for (int i = 0; i < 4; i++)
                #pragma unroll
                for (int j = 0; j < 4; j++)
                    s[i][j] = fmaf(qm[i], km[j], s[i][j]);
        }

        __syncthreads();  // everyone done reading KPs as K; safe to overwrite with P

        // Online softmax (row groups = 16 threads sharing ty, lanes (ty&1)*16+tx)
        #pragma unroll
        for (int i = 0; i < 4; i++) {
            float rm = fmaxf(fmaxf(s[i][0], s[i][1]), fmaxf(s[i][2], s[i][3])) * scale;
            rm = fmaxf(rm, __shfl_xor_sync(0xffffffffu, rm, 1));
            rm = fmaxf(rm, __shfl_xor_sync(0xffffffffu, rm, 2));
            rm = fmaxf(rm, __shfl_xor_sync(0xffffffffu, rm, 4));
            rm = fmaxf(rm, __shfl_xor_sync(0xffffffffu, rm, 8));
            float mnew = fmaxf(m_i[i], rm);
            float corr = __expf(m_i[i] - mnew);
            float rs = 0.f;
            #pragma unroll
            for (int j = 0; j < 4; j++) {
                s[i][j] = __expf(fmaf(s[i][j], scale, -mnew));
                rs += s[i][j];
            }
            rs += __shfl_xor_sync(0xffffffffu, rs, 1);
            rs += __shfl_xor_sync(0xffffffffu, rs, 2);
            rs += __shfl_xor_sync(0xffffffffu, rs, 4);
            rs += __shfl_xor_sync(0xffffffffu, rs, 8);
            l_i[i] = l_i[i] * corr + rs;
            m_i[i] = mnew;
            #pragma unroll
            for (int j = 0; j < 4; j++) o[i][j] *= corr;
            // Store P row-major [m][n] — float4, conflict-free
            *(float4*)&KPs[ty * 4 + i][tx * 4] =
                make_float4(s[i][0], s[i][1], s[i][2], s[i][3]);
        }
        __syncthreads();

        // O += P @ V
        #pragma unroll 8
        for (int n = 0; n < 64; n++) {
            float4 vv = *(const float4*)&Vs[n][tx * 4];
            float vm[4] = {vv.x, vv.y, vv.z, vv.w};
            float pm[4];
            #pragma unroll
            for (int i = 0; i < 4; i++) pm[i] = KPs[ty * 4 + i][n];
            #pragma unroll
            for (int i = 0; i < 4; i++)
                #pragma unroll
                for (int j = 0; j < 4; j++)
                    o[i][j] = fmaf(pm[i], vm[j], o[i][j]);
        }
    }

    // Epilogue: normalize and write ctx in [B,T,D] layout
    #pragma unroll
    for (int i = 0; i < 4; i++) {
        float inv = 1.f / l_i[i];
        int t = q0 + ty * 4 + i;
        #pragma unroll
        for (int j = 0; j < 4; j++) {
            g_ctx[(size_t)(b * T_ + t) * D_ + h * DH_ + tx * 4 + j] = o[i][j] * inv;
        }
    }
}

// ---------------------------------------------------------------------------
extern "C" void kernel_launch(void* const* d_in, const int* in_sizes, int n_in,
                              void* d_out, int out_size)
{
    const float* x     = (const float*)d_in[0];
    const float* qkv_w = (const float*)d_in[1];
    const float* qkv_b = (const float*)d_in[2];
    const float* out_w = (const float*)d_in[3];
    const float* out_b = (const float*)d_in[4];
    float* out = (float*)d_out;

    // QKV projection + scatter: M=8192, N=3072, K=1024
    gemm_kernel<0><<<dim3(3 * D_ / 64, M_ / 64), 256>>>(
        x, qkv_w, qkv_b, nullptr, M_, 3 * D_, D_);

    // Flash attention: grid (T/64, H, B)
    attn_kernel<<<dim3(T_ / 64, H_, B_), 256>>>();

    // Output projection: M=8192, N=1024, K=1024
    gemm_kernel<1><<<dim3(D_ / 64, M_ / 64), 256>>>(
        nullptr, out_w, out_b, out, M_, D_, D_);
}

// round 12
// speedup vs baseline: 1.0013x; 1.0011x over previous
#include <cuda_runtime.h>

#define B_  4
#define T_  2048
#define D_  1024
#define H_  16
#define DH_ 64
#define M_  (B_*T_)   // 8192

// Scratch (allocation-free rule: device globals)
__device__ float g_q[B_*H_*T_*DH_];
__device__ float g_k[B_*H_*T_*DH_];
__device__ float g_v[B_*H_*T_*DH_];
__device__ float g_ctx[M_*D_];

// ---------------------------------------------------------------------------
// GEMM: C[M,N] = A[M,K] @ W[N,K]^T + bias[N]
// MODE 0: A = x param, scatter result into g_q/g_k/g_v ([B,H,T,dh])
// MODE 1: A = g_ctx,   write result into C param (plain row-major)
// 64x64 tile, BK=16, 256 threads, 4x4 per-thread tile.
// ---------------------------------------------------------------------------
template<int MODE>
__global__ __launch_bounds__(256)
void gemm_kernel(const float* __restrict__ A, const float* __restrict__ W,
                 const float* __restrict__ bias, float* __restrict__ C,
                 int M, int N, int K)
{
    __shared__ float As[16][64];   // [k][m]
    __shared__ float Bs[16][64];   // [k][n]

    const float* Ap = (MODE == 1) ? (const float*)g_ctx : A;

    int tid = threadIdx.x;
    int tx = tid & 15;
    int ty = tid >> 4;
    int m0 = blockIdx.y * 64;
    int n0 = blockIdx.x * 64;

    int lr = tid >> 2;          // 0..63 row within tile
    int lc = (tid & 3) << 2;    // 0,4,8,12 col within BK

    float acc[4][4] = {};

    for (int kt = 0; kt < K; kt += 16) {
        float4 a4 = *(const float4*)&Ap[(size_t)(m0 + lr) * K + kt + lc];
        float4 b4 = *(const float4*)&W [(size_t)(n0 + lr) * K + kt + lc];
        As[lc + 0][lr] = a4.x; As[lc + 1][lr] = a4.y;
        As[lc + 2][lr] = a4.z; As[lc + 3][lr] = a4.w;
        Bs[lc + 0][lr] = b4.x; Bs[lc + 1][lr] = b4.y;
        Bs[lc + 2][lr] = b4.z; Bs[lc + 3][lr] = b4.w;
        __syncthreads();

        #pragma unroll
        for (int kk = 0; kk < 16; kk++) {
            float4 av = *(const float4*)&As[kk][ty * 4];
            float4 bv = *(const float4*)&Bs[kk][tx * 4];
            float am[4] = {av.x, av.y, av.z, av.w};
            float bm[4] = {bv.x, bv.y, bv.z, bv.w};
            #pragma unroll
            for (int i = 0; i < 4; i++)
                #pragma unroll
                for (int j = 0; j < 4; j++)
                    acc[i][j] = fmaf(am[i], bm[j], acc[i][j]);
        }
        __syncthreads();
    }

    #pragma unroll
    for (int i = 0; i < 4; i++) {
        int m = m0 + ty * 4 + i;
        #pragma unroll
        for (int j = 0; j < 4; j++) {
            int n = n0 + tx * 4 + j;
            float val = acc[i][j] + bias[n];
            if (MODE == 0) {
                // n = which*D + h*64 + d ;  m = b*T + t
                int bb    = m >> 11;        // /2048
                int t     = m & 2047;
                int which = n >> 10;
                int rem   = n & 1023;
                int hh    = rem >> 6;
                int dd    = rem & 63;
                int idx   = ((bb * H_ + hh) * T_ + t) * DH_ + dd;
                float* dst = (which == 0) ? g_q : (which == 1) ? g_k : g_v;
                dst[idx] = val;
            } else {
                C[(size_t)m * N + n] = val;
            }
        }
    }
}

// ---------------------------------------------------------------------------
// Flash attention, fp32. Block = (b, h, 64 q rows). K/V tiles of 64 rows.
// Smem: Qs [d][m] 16KB, KPs (K as [d][n], reused as P [m][n]) 16KB, Vs [n][d]
// 16KB = 48KB exactly. 256 threads: (ty 0..15 -> 4 q rows, tx 0..15 -> 4 cols).
// Row reductions via shfl_xor within 16-lane half-warps (lane = (ty&1)*16+tx).
// ---------------------------------------------------------------------------
__global__ __launch_bounds__(256)
void attn_kernel()
{
    __shared__ float Qs [64][64];   // [d][m]
    __shared__ float KPs[64][64];   // K: [d][n]  ->  P: [m][n]
    __shared__ float Vs [64][64];   // [n][d]

    int tid = threadIdx.x;
    int tx = tid & 15;
    int ty = tid >> 4;
    int b = blockIdx.z;
    int h = blockIdx.y;
    int q0 = blockIdx.x * 64;

    const float* Qg = g_q + (size_t)(b * H_ + h) * T_ * DH_;
    const float* Kg = g_k + (size_t)(b * H_ + h) * T_ * DH_;
    const float* Vg = g_v + (size_t)(b * H_ + h) * T_ * DH_;

    int lr  = tid >> 2;          // 0..63
    int lc0 = (tid & 3) * 16;    // 0,16,32,48

    // Load Q tile, transposed to [d][m]
    #pragma unroll
    for (int j = 0; j < 4; j++) {
        float4 v = *(const float4*)&Qg[(q0 + lr) * DH_ + lc0 + j * 4];
        Qs[lc0 + j*4 + 0][lr] = v.x;
        Qs[lc0 + j*4 + 1][lr] = v.y;
        Qs[lc0 + j*4 + 2][lr] = v.z;
        Qs[lc0 + j*4 + 3][lr] = v.w;
    }

    float m_i[4], l_i[4], o[4][4];
    #pragma unroll
    for (int i = 0; i < 4; i++) {
        m_i[i] = -1e30f;
        l_i[i] = 0.f;
        #pragma unroll
        for (int j = 0; j < 4; j++) o[i][j] = 0.f;
    }

    const float scale = 0.125f;  // 1/sqrt(64)

    for (int k0 = 0; k0 < T_; k0 += 64) {
        __syncthreads();  // prior iter's P/V reads done; also covers Q load on iter 0

        // Load K (transposed [d][n]) and V (natural [n][d])
        #pragma unroll
        for (int j = 0; j < 4; j++) {
            float4 kv = *(const float4*)&Kg[(k0 + lr) * DH_ + lc0 + j * 4];
            KPs[lc0 + j*4 + 0][lr] = kv.x;
            KPs[lc0 + j*4 + 1][lr] = kv.y;
            KPs[lc0 + j*4 + 2][lr] = kv.z;
            KPs[lc0 + j*4 + 3][lr] = kv.w;
            float4 vv = *(const float4*)&Vg[(k0 + lr) * DH_ + lc0 + j * 4];
            *(float4*)&Vs[lr][lc0 + j * 4] = vv;
        }
        __syncthreads();

        // S = Q @ K^T  (4x4 per thread)
        float s[4][4] = {};
        #pragma unroll 8
        for (int d = 0; d < 64; d++) {
            float4 qv = *(const float4*)&Qs[d][ty * 4];
            float4 kv = *(const float4*)&KPs[d][tx * 4];
            float qm[4] = {qv.x, qv.y, qv.z, qv.w};
            float km[4] = {kv.x, kv.y, kv.z, kv.w};
            #pragma unroll
            for (int i = 0; i < 4; i++)
                #pragma unroll
                for (int j = 0; j < 4; j++)
                    s[i][j] = fmaf(qm[i], km[j], s[i][j]);
        }

        __syncthreads();  // everyone done reading KPs as K; safe to overwrite with P

        // Online softmax (row groups = 16 threads sharing ty, lanes (ty&1)*16+tx)
        #pragma unroll
        for (int i = 0; i < 4; i++) {
            float rm = fmaxf(fmaxf(s[i][0], s[i][1]), fmaxf(s[i][2], s[i][3])) * scale;
            rm = fmaxf(rm, __shfl_xor_sync(0xffffffffu, rm, 1));
            rm = fmaxf(rm, __shfl_xor_sync(0xffffffffu, rm, 2));
            rm = fmaxf(rm, __shfl_xor_sync(0xffffffffu, rm, 4));
            rm = fmaxf(rm, __shfl_xor_sync(0xffffffffu, rm, 8));
            float mnew = fmaxf(m_i[i], rm);
            float corr = __expf(m_i[i] - mnew);
            float rs = 0.f;
            #pragma unroll
            for (int j = 0; j < 4; j++) {
                s[i][j] = __expf(fmaf(s[i][j], scale, -mnew));
                rs += s[i][j];
            }
            rs += __shfl_xor_sync(0xffffffffu, rs, 1);
            rs += __shfl_xor_sync(0xffffffffu, rs, 2);
            rs += __shfl_xor_sync(0xffffffffu, rs, 4);
            rs += __shfl_xor_sync(0xffffffffu, rs, 8);
            l_i[i] = l_i[i] * corr + rs;
            m_i[i] = mnew;
            #pragma unroll
            for (int j = 0; j < 4; j++) o[i][j] *= corr;
            // Store P row-major [m][n] — float4, conflict-free
            *(float4*)&KPs[ty * 4 + i][tx * 4] =
                make_float4(s[i][0], s[i][1], s[i][2], s[i][3]);
        }
        __syncthreads();

        // O += P @ V
        #pragma unroll 8
        for (int n = 0; n < 64; n++) {
            float4 vv = *(const float4*)&Vs[n][tx * 4];
            float vm[4] = {vv.x, vv.y, vv.z, vv.w};
            float pm[4];
            #pragma unroll
            for (int i = 0; i < 4; i++) pm[i] = KPs[ty * 4 + i][n];
            #pragma unroll
            for (int i = 0; i < 4; i++)
                #pragma unroll
                for (int j = 0; j < 4; j++)
                    o[i][j] = fmaf(pm[i], vm[j], o[i][j]);
        }
    }

    // Epilogue: normalize and write ctx in [B,T,D] layout
    #pragma unroll
    for (int i = 0; i < 4; i++) {
        float inv = 1.f / l_i[i];
        int t = q0 + ty * 4 + i;
        #pragma unroll
        for (int j = 0; j < 4; j++) {
            g_ctx[(size_t)(b * T_ + t) * D_ + h * DH_ + tx * 4 + j] = o[i][j] * inv;
        }
    }
}

// ---------------------------------------------------------------------------
extern "C" void kernel_launch(void* const* d_in, const int* in_sizes, int n_in,
                              void* d_out, int out_size)
{
    const float* x     = (const float*)d_in[0];
    const float* qkv_w = (const float*)d_in[1];
    const float* qkv_b = (const float*)d_in[2];
    const float* out_w = (const float*)d_in[3];
    const float* out_b = (const float*)d_in[4];
    float* out = (float*)d_out;

    // QKV projection + scatter: M=8192, N=3072, K=1024
    gemm_kernel<0><<<dim3(3 * D_ / 64, M_ / 64), 256>>>(
        x, qkv_w, qkv_b, nullptr, M_, 3 * D_, D_);

    // Flash attention: grid (T/64, H, B)
    attn_kernel<<<dim3(T_ / 64, H_, B_), 256>>>();

    // Output projection: M=8192, N=1024, K=1024
    gemm_kernel<1><<<dim3(D_ / 64, M_ / 64), 256>>>(
        nullptr, out_w, out_b, out, M_, D_, D_);
}